// round 14
// baseline (speedup 1.0000x reference)
#include <cuda_runtime.h>
#include <cuda_bf16.h>
#include <cstdint>

#define B_  512
#define M_  16
#define D_  128
#define P_  16
#define T_  4096
#define R_  (B_*M_)          // 8192 rows

// ---- device-global scratch (no allocations allowed) ----
__device__ __nv_bfloat16 g_nsh[R_ * D_];
__device__ __nv_bfloat16 g_nsl[R_ * D_];
__device__ __nv_bfloat16 g_tjh[T_ * D_];
__device__ __nv_bfloat16 g_tjl[T_ * D_];
__device__ float g_ssq[R_];
__device__ float g_tsq[T_];

// ---------------------------------------------------------------- helpers
__device__ __forceinline__ uint32_t smem_u32(const void* p) {
    uint32_t a;
    asm("{ .reg .u64 t; cvta.to.shared.u64 t, %1; cvt.u32.u64 %0, t; }" : "=r"(a) : "l"(p));
    return a;
}
__device__ __forceinline__ float ex2a(float x) {
    float r; asm("ex2.approx.f32 %0, %1;" : "=f"(r) : "f"(x)); return r;
}
__device__ __forceinline__ float rcpa(float x) {
    float r; asm("rcp.approx.f32 %0, %1;" : "=f"(r) : "f"(x)); return r;
}
__device__ __forceinline__ float fast_tanh(float x) {
    const float TWO_L2E = 2.8853900817779268f;
    float e = ex2a(x * TWO_L2E);
    return fmaf(-2.0f, rcpa(e + 1.0f), 1.0f);
}
__device__ __forceinline__ void cpasync16(uint32_t s, const void* g) {
    asm volatile("cp.async.cg.shared.global [%0], [%1], 16;" :: "r"(s), "l"(g));
}
#define CP_COMMIT() asm volatile("cp.async.commit_group;" ::: "memory")
#define CP_WAIT(n)  asm volatile("cp.async.wait_group %0;" :: "n"(n) : "memory")

__device__ __forceinline__ void ldsm4(uint32_t* r, uint32_t a) {
    asm volatile("ldmatrix.sync.aligned.m8n8.x4.shared.b16 {%0,%1,%2,%3}, [%4];"
        : "=r"(r[0]), "=r"(r[1]), "=r"(r[2]), "=r"(r[3]) : "r"(a));
}
__device__ __forceinline__ void ldsm4t(uint32_t* r, uint32_t a) {
    asm volatile("ldmatrix.sync.aligned.m8n8.x4.trans.shared.b16 {%0,%1,%2,%3}, [%4];"
        : "=r"(r[0]), "=r"(r[1]), "=r"(r[2]), "=r"(r[3]) : "r"(a));
}
__device__ __forceinline__ void mma_bf16(float* d, const uint32_t* a, const uint32_t* b) {
    asm volatile(
        "mma.sync.aligned.m16n8k16.row.col.f32.bf16.bf16.f32 "
        "{%0,%1,%2,%3}, {%4,%5,%6,%7}, {%8,%9}, {%0,%1,%2,%3};"
        : "+f"(d[0]), "+f"(d[1]), "+f"(d[2]), "+f"(d[3])
        : "r"(a[0]), "r"(a[1]), "r"(a[2]), "r"(a[3]), "r"(b[0]), "r"(b[1]));
}
__device__ __forceinline__ void split4(float4 v, uint32_t& hp0, uint32_t& hp1,
                                       uint32_t& lp0, uint32_t& lp1) {
    __nv_bfloat16 h0 = __float2bfloat16_rn(v.x), h1 = __float2bfloat16_rn(v.y);
    __nv_bfloat16 h2 = __float2bfloat16_rn(v.z), h3 = __float2bfloat16_rn(v.w);
    __nv_bfloat16 l0 = __float2bfloat16_rn(v.x - __bfloat162float(h0));
    __nv_bfloat16 l1 = __float2bfloat16_rn(v.y - __bfloat162float(h1));
    __nv_bfloat16 l2 = __float2bfloat16_rn(v.z - __bfloat162float(h2));
    __nv_bfloat16 l3 = __float2bfloat16_rn(v.w - __bfloat162float(h3));
    hp0 = (uint32_t)__bfloat16_as_ushort(h0) | ((uint32_t)__bfloat16_as_ushort(h1) << 16);
    hp1 = (uint32_t)__bfloat16_as_ushort(h2) | ((uint32_t)__bfloat16_as_ushort(h3) << 16);
    lp0 = (uint32_t)__bfloat16_as_ushort(l0) | ((uint32_t)__bfloat16_as_ushort(l1) << 16);
    lp1 = (uint32_t)__bfloat16_as_ushort(l2) | ((uint32_t)__bfloat16_as_ushort(l3) << 16);
}

// ---------------------------------------------------------------------------
// Kernel 1: fused prep, SINGLE WAVE (grid 128, 1 CTA/SM):
// each CTA first converts its 32 trajectory rows (hi/lo + tsq), then runs the
// ns HMMA tile (m = x>>3, 64 rows b0 = (x&7)*64). Layout/MMA identical to R10.
// ---------------------------------------------------------------------------
#define PS_STRIDE 304
#define PW_STRIDE 272
#define POFF_SL  19456
#define POFF_WH  38912
#define POFF_WL  78080
#define POFF_SSQ 117248
#define PREP_SMEM 117504

__global__ __launch_bounds__(256) void prep_kernel(
    const float* __restrict__ phi, const float* __restrict__ state,
    const float* __restrict__ A,   const float* __restrict__ Bin,
    const float* __restrict__ tj,  float* __restrict__ tail)
{
    const int tid = threadIdx.x;
    extern __shared__ __align__(1024) char smem[];
    const uint32_t sb = smem_u32(smem);
    const int m  = blockIdx.x >> 3;
    const int b0 = (blockIdx.x & 7) * 64;
    const int wid = tid >> 5;
    const int lid = tid & 31;
    const int warp_m = (wid >> 2) * 32;
    const int warp_n = (wid & 3) * 32;

    // ---- inline trajectory part: 32 rows per CTA (8 warps x 4 rows)
    {
        const int blk = blockIdx.x;
#pragma unroll
        for (int rr = 0; rr < 4; rr++) {
            const int row = blk * 32 + wid * 4 + rr;
            float4 v = reinterpret_cast<const float4*>(tj)[row * 32 + lid];
            uint32_t hp0, hp1, lp0, lp1;
            split4(v, hp0, hp1, lp0, lp1);
            uint32_t* oh = reinterpret_cast<uint32_t*>(g_tjh) + row * 64 + lid * 2;
            uint32_t* ol = reinterpret_cast<uint32_t*>(g_tjl) + row * 64 + lid * 2;
            oh[0] = hp0; oh[1] = hp1;
            ol[0] = lp0; ol[1] = lp1;
            float s = v.x*v.x + v.y*v.y + v.z*v.z + v.w*v.w;
#pragma unroll
            for (int o = 16; o > 0; o >>= 1) s += __shfl_xor_sync(0xFFFFFFFFu, s, o);
            if (lid == 0) g_tsq[row] = s;
        }
    }

    // ---- ns part (R10 verbatim)
    if (tid < 64) reinterpret_cast<float*>(smem + POFF_SSQ)[tid] = 0.0f;

    {
        const float4* s4 = reinterpret_cast<const float4*>(state);
        for (int i = tid; i < 64 * 32; i += 256) {
            int r = i >> 5, c4 = i & 31;
            float4 v = s4[(b0 + r) * 32 + c4];
            uint32_t h0, h1, l0, l1;
            split4(v, h0, h1, l0, l1);
            uint32_t off = (uint32_t)r * PS_STRIDE + (uint32_t)c4 * 8;
            *reinterpret_cast<uint2*>(smem + off)           = make_uint2(h0, h1);
            *reinterpret_cast<uint2*>(smem + POFF_SL + off) = make_uint2(l0, l1);
        }
        const float4* p4 = reinterpret_cast<const float4*>(phi);
        for (int i = tid; i < 64 * 4; i += 256) {
            int r = i >> 2, c4 = i & 3;
            float4 v = p4[(b0 + r) * 4 + c4];
            uint32_t h0, h1, l0, l1;
            split4(v, h0, h1, l0, l1);
            uint32_t off = (uint32_t)r * PS_STRIDE + 256u + (uint32_t)c4 * 8;
            *reinterpret_cast<uint2*>(smem + off)           = make_uint2(h0, h1);
            *reinterpret_cast<uint2*>(smem + POFF_SL + off) = make_uint2(l0, l1);
        }
        const float4* a4 = reinterpret_cast<const float4*>(A) + (size_t)m * 4096;
        for (int i = tid; i < 128 * 32; i += 256) {
            int dd = i >> 5, c4 = i & 31;
            float4 v = a4[dd * 32 + c4];
            uint32_t h0, h1, l0, l1;
            split4(v, h0, h1, l0, l1);
            uint32_t off = (uint32_t)dd * PW_STRIDE + (uint32_t)c4 * 8;
            *reinterpret_cast<uint2*>(smem + POFF_WH + off) = make_uint2(h0, h1);
            *reinterpret_cast<uint2*>(smem + POFF_WL + off) = make_uint2(l0, l1);
        }
        const float4* b4 = reinterpret_cast<const float4*>(Bin) + (size_t)m * 512;
        for (int i = tid; i < 16 * 32; i += 256) {
            int p = i >> 5, c4 = i & 31;
            float4 v = b4[p * 32 + c4];
            uint32_t h0, h1, l0, l1;
            split4(v, h0, h1, l0, l1);
            uint32_t off = (uint32_t)(128 + p) * PW_STRIDE + (uint32_t)c4 * 8;
            *reinterpret_cast<uint2*>(smem + POFF_WH + off) = make_uint2(h0, h1);
            *reinterpret_cast<uint2*>(smem + POFF_WL + off) = make_uint2(l0, l1);
        }
    }
    __syncthreads();

    float d[2][4][4];
#pragma unroll
    for (int a = 0; a < 2; a++)
#pragma unroll
        for (int b = 0; b < 4; b++)
#pragma unroll
            for (int c = 0; c < 4; c++) d[a][b][c] = 0.0f;

    const uint32_t aRow  = (uint32_t)(warp_m + (lid & 15)) * PS_STRIDE + ((uint32_t)(lid >> 4) & 1) * 16u;
    const uint32_t bKrow = (uint32_t)(lid & 15) * PW_STRIDE;
    const uint32_t bNcol = ((uint32_t)warp_n + (((uint32_t)lid >> 4) & 1) * 8u) * 2u;

#pragma unroll
    for (int ks = 0; ks < 9; ks++) {
        uint32_t bqh[2][4], bql[2][4];
#pragma unroll
        for (int np = 0; np < 2; np++) {
            const uint32_t bo = sb + POFF_WH + (uint32_t)ks * 16u * PW_STRIDE
                              + bKrow + bNcol + (uint32_t)np * 32u;
            ldsm4t(bqh[np], bo);
            ldsm4t(bql[np], bo + (POFF_WL - POFF_WH));
        }
#pragma unroll
        for (int mt = 0; mt < 2; mt++) {
            uint32_t ah[4], al[4];
            const uint32_t ao = sb + aRow + (uint32_t)mt * 16u * PS_STRIDE + (uint32_t)ks * 32u;
            ldsm4(ah, ao);
            ldsm4(al, ao + POFF_SL);
#pragma unroll
            for (int nt = 0; nt < 4; nt++) {
                const uint32_t* bh = &bqh[nt >> 1][(nt & 1) * 2];
                const uint32_t* bl = &bql[nt >> 1][(nt & 1) * 2];
                mma_bf16(d[mt][nt], ah, bh);
                mma_bf16(d[mt][nt], ah, bl);
                mma_bf16(d[mt][nt], al, bh);
            }
        }
    }

    float* ssq_s = reinterpret_cast<float*>(smem + POFF_SSQ);
#pragma unroll
    for (int mt = 0; mt < 2; mt++) {
        const int lr  = warp_m + mt * 16 + (lid >> 2);
        const int rg0 = (b0 + lr) * M_ + m;
        const int rg1 = (b0 + lr + 8) * M_ + m;
        float s0 = 0.0f, s1 = 0.0f;
#pragma unroll
        for (int nt = 0; nt < 4; nt++) {
            const int lc = warp_n + nt * 8 + (lid & 3) * 2;
            float v0 = fast_tanh(d[mt][nt][0]);
            float v1 = fast_tanh(d[mt][nt][1]);
            float v2 = fast_tanh(d[mt][nt][2]);
            float v3 = fast_tanh(d[mt][nt][3]);
            s0 += v0 * v0 + v1 * v1;
            s1 += v2 * v2 + v3 * v3;
            __nv_bfloat16 h0 = __float2bfloat16_rn(v0), h1 = __float2bfloat16_rn(v1);
            __nv_bfloat16 h2 = __float2bfloat16_rn(v2), h3 = __float2bfloat16_rn(v3);
            uint32_t hp0 = (uint32_t)__bfloat16_as_ushort(h0) | ((uint32_t)__bfloat16_as_ushort(h1) << 16);
            uint32_t hp1 = (uint32_t)__bfloat16_as_ushort(h2) | ((uint32_t)__bfloat16_as_ushort(h3) << 16);
            __nv_bfloat16 q0 = __float2bfloat16_rn(v0 - __bfloat162float(h0));
            __nv_bfloat16 q1 = __float2bfloat16_rn(v1 - __bfloat162float(h1));
            __nv_bfloat16 q2 = __float2bfloat16_rn(v2 - __bfloat162float(h2));
            __nv_bfloat16 q3 = __float2bfloat16_rn(v3 - __bfloat162float(h3));
            uint32_t lp0 = (uint32_t)__bfloat16_as_ushort(q0) | ((uint32_t)__bfloat16_as_ushort(q1) << 16);
            uint32_t lp1 = (uint32_t)__bfloat16_as_ushort(q2) | ((uint32_t)__bfloat16_as_ushort(q3) << 16);
            *reinterpret_cast<uint32_t*>(g_nsh + (size_t)rg0 * D_ + lc) = hp0;
            *reinterpret_cast<uint32_t*>(g_nsh + (size_t)rg1 * D_ + lc) = hp1;
            *reinterpret_cast<uint32_t*>(g_nsl + (size_t)rg0 * D_ + lc) = lp0;
            *reinterpret_cast<uint32_t*>(g_nsl + (size_t)rg1 * D_ + lc) = lp1;
            if (tail) {
                *reinterpret_cast<float2*>(tail + (size_t)rg0 * D_ + lc) = make_float2(v0, v1);
                *reinterpret_cast<float2*>(tail + (size_t)rg1 * D_ + lc) = make_float2(v2, v3);
            }
        }
        s0 += __shfl_xor_sync(0xFFFFFFFFu, s0, 1);
        s0 += __shfl_xor_sync(0xFFFFFFFFu, s0, 2);
        s1 += __shfl_xor_sync(0xFFFFFFFFu, s1, 1);
        s1 += __shfl_xor_sync(0xFFFFFFFFu, s1, 2);
        if ((lid & 3) == 0) {
            atomicAdd(&ssq_s[lr], s0);
            atomicAdd(&ssq_s[lr + 8], s1);
        }
    }
    __syncthreads();
    if (tid < 64) g_ssq[(b0 + tid) * M_ + m] = ssq_s[tid];
}

// ---------------------------------------------------------------------------
// Kernel 2 (R10 verbatim — measured best): A-resident (hi+lo, full K) +
// 2 t-tiles, B double-buffered in k32 chunks, two syncs/chunk,
// fill-after-compute, norms in smem. 99840 B -> 2 CTAs/SM.
// ---------------------------------------------------------------------------
#define OFF_AL   32768
#define OFF_B    65536
#define BSTG     16384
#define OFF_SSQ  98304
#define OFF_TSQ  98816
#define SMEM_BYTES 99840
#define NTILE 2
#define NCHUNK (NTILE * 4)

__global__ __launch_bounds__(256, 2) void sim_mma_kernel(float* __restrict__ out)
{
    extern __shared__ __align__(1024) char smem[];
    const uint32_t sb = smem_u32(smem);
    const int tid = threadIdx.x;
    const int wid = tid >> 5;
    const int lid = tid & 31;
    const int warp_m = (wid >> 2) * 64;
    const int warp_n = (wid & 3) * 32;
    const int r0 = blockIdx.y * 128;
    const int t0 = blockIdx.x * (NTILE * 128);

    // ---- A resident fill (one commit group)
    {
        const __nv_bfloat16* srcH = g_nsh + (size_t)r0 * D_;
        const __nv_bfloat16* srcL = g_nsl + (size_t)r0 * D_;
#pragma unroll
        for (int it = 0; it < 8; it++) {
            int i = tid + it * 256;           // 0..2047
            int r = i >> 4, g = i & 15;
            uint32_t dst = (uint32_t)r * 256u + (uint32_t)((g ^ (r & 7)) << 4);
            cpasync16(sb + dst,           srcH + r * D_ + g * 8);
            cpasync16(sb + OFF_AL + dst,  srcL + r * D_ + g * 8);
        }
    }
    CP_COMMIT();

    // fill B k32 chunk c (0..NCHUNK-1) into slot c&1
    auto fillB = [&](int c) {
        const uint32_t sbase = sb + OFF_B + (uint32_t)(c & 1) * BSTG;
        const int tile = c >> 2, kc = c & 3;
        const __nv_bfloat16* srcH = g_tjh + (size_t)(t0 + tile * 128) * D_ + kc * 32;
        const __nv_bfloat16* srcL = g_tjl + (size_t)(t0 + tile * 128) * D_ + kc * 32;
#pragma unroll
        for (int it = 0; it < 4; it++) {
            int idx = tid + it * 256;          // 0..1023
            int hl = idx >> 9, rem = idx & 511;
            int r = rem >> 2, cc = rem & 3;
            uint32_t slot = (uint32_t)(cc ^ (r & 3) ^ (((r >> 2) & 1) << 1));
            uint32_t dst = sbase + (uint32_t)hl * 8192u + (uint32_t)r * 64u + (slot << 4);
            cpasync16(dst, (hl ? srcL : srcH) + r * D_ + cc * 8);
        }
    };

    fillB(0); CP_COMMIT();
    fillB(1); CP_COMMIT();

    // norms
    if (tid < 128) reinterpret_cast<float*>(smem + OFF_SSQ)[tid] = g_ssq[r0 + tid];
    reinterpret_cast<float*>(smem + OFF_TSQ)[tid] = g_tsq[t0 + tid];

    float d[4][4][4];
#pragma unroll
    for (int a = 0; a < 4; a++)
#pragma unroll
        for (int b = 0; b < 4; b++)
#pragma unroll
            for (int c = 0; c < 4; c++) d[a][b][c] = 0.0f;

    // per-lane addressing
    const uint32_t ra = (uint32_t)(warp_m + (lid & 15));
    const uint32_t aSel = (lid >> 4) & 1;
    const uint32_t rxA = (ra & 7);
    uint32_t aBase[4];
#pragma unroll
    for (int mt = 0; mt < 4; mt++) aBase[mt] = sb + (ra + mt * 16) * 256u;
    const uint32_t rb = (uint32_t)(warp_n + ((lid & 16) >> 1) + (lid & 7));
    const uint32_t bSel = (lid >> 3) & 1;
    const uint32_t rxB = (rb & 3) ^ (((rb >> 2) & 1) << 1);
    uint32_t rowOffB[2];
#pragma unroll
    for (int np = 0; np < 2; np++) rowOffB[np] = (rb + np * 16) * 64u;

    const float* s_ssq = reinterpret_cast<const float*>(smem + OFF_SSQ);
    const float* s_tsq = reinterpret_cast<const float*>(smem + OFF_TSQ);
    const float NL2E = -1.4426950408889634f;
    const float SC64 = 5.421010862427522e-20f;

#pragma unroll
    for (int i = 0; i < NCHUNK; i++) {
        if (i == 0)              { CP_WAIT(1); }   // A + B0 done, B1 pending
        else if (i < NCHUNK - 1) { CP_WAIT(1); }   // B(i) done, B(i+1) pending
        else                     { CP_WAIT(0); }
        __syncthreads();

        const uint32_t sbs = sb + OFF_B + (uint32_t)(i & 1) * BSTG;
#pragma unroll
        for (int ksub = 0; ksub < 2; ksub++) {
            const uint32_t cB = (uint32_t)(ksub * 2) + bSel;
            uint32_t bqh[2][4], bql[2][4];
#pragma unroll
            for (int np = 0; np < 2; np++) {
                const uint32_t bo = sbs + rowOffB[np] + (((cB ^ rxB)) << 4);
                ldsm4(bqh[np], bo);
                ldsm4(bql[np], bo + 8192u);
            }
            const int ks16 = (i & 3) * 2 + ksub;         // 0..7 within K=128
            const uint32_t gsel = (uint32_t)(((uint32_t)(ks16 * 2) + aSel) ^ rxA) << 4;
#pragma unroll
            for (int mt = 0; mt < 4; mt++) {
                uint32_t ah[4], al[4];
                ldsm4(ah, aBase[mt] + gsel);
                ldsm4(al, aBase[mt] + OFF_AL + gsel);
#pragma unroll
                for (int nt = 0; nt < 4; nt++) {
                    const uint32_t* bh = &bqh[nt >> 1][(nt & 1) * 2];
                    const uint32_t* bl = &bql[nt >> 1][(nt & 1) * 2];
                    mma_bf16(d[mt][nt], ah, bh);
                    mma_bf16(d[mt][nt], ah, bl);
                    mma_bf16(d[mt][nt], al, bh);
                }
            }
        }

        // ---- per-t-tile epilogue after last chunk of the tile
        if ((i & 3) == 3) {
            const int tile = i >> 2;
#pragma unroll
            for (int mt = 0; mt < 4; mt++) {
                const int lr = warp_m + mt * 16 + (lid >> 2);
                const float sq0 = s_ssq[lr];
                const float sq1 = s_ssq[lr + 8];
                float* row0 = out + (size_t)(r0 + lr) * T_ + t0 + tile * 128;
                float* row1 = row0 + (size_t)8 * T_;
#pragma unroll
                for (int nt = 0; nt < 4; nt++) {
                    const int lc = warp_n + nt * 8 + (lid & 3) * 2;
                    const float tq0 = s_tsq[tile * 128 + lc];
                    const float tq1 = s_tsq[tile * 128 + lc + 1];
                    float in[4] = { sq0 + tq0, sq0 + tq1, sq1 + tq0, sq1 + tq1 };
                    float o[4];
#pragma unroll
                    for (int j = 0; j < 4; j++) {
                        float dd = fmaf(-2.0f, d[mt][nt][j], in[j]);
                        dd = fmaxf(dd, 0.0f);
                        float t = NL2E * dd;
                        float tb = t, sc = 1.0f;
                        if (t < -80.0f) { tb = t + 64.0f; sc = SC64; }
                        o[j] = ex2a(tb) * sc;
                        d[mt][nt][j] = 0.0f;
                    }
                    *reinterpret_cast<float2*>(row0 + lc) = make_float2(o[0], o[1]);
                    *reinterpret_cast<float2*>(row1 + lc) = make_float2(o[2], o[3]);
                }
            }
        }
        __syncthreads();                    // slot i&1 fully consumed
        if (i + 2 < NCHUNK) { fillB(i + 2); CP_COMMIT(); }
    }
}

// ---------------------------------------------------------------------------
extern "C" void kernel_launch(void* const* d_in, const int* in_sizes, int n_in,
                              void* d_out, int out_size) {
    const float *phi = nullptr, *state = nullptr, *traj = nullptr, *A = nullptr, *Bin = nullptr;
    for (int i = 0; i < n_in; i++) {
        switch (in_sizes[i]) {
            case B_ * P_:      phi   = (const float*)d_in[i]; break;  // 8192
            case B_ * D_:      state = (const float*)d_in[i]; break;  // 65536
            case T_ * D_:      traj  = (const float*)d_in[i]; break;  // 524288
            case M_ * D_ * D_: A     = (const float*)d_in[i]; break;  // 262144
            case M_ * P_ * D_: Bin   = (const float*)d_in[i]; break;  // 32768
        }
    }
    float* out = (float*)d_out;
    const long long SIMSZ = (long long)R_ * T_;
    const long long NSSZ  = (long long)R_ * D_;
    float* tail = ((long long)out_size >= SIMSZ + NSSZ) ? out + SIMSZ : nullptr;

    cudaFuncSetAttribute(prep_kernel, cudaFuncAttributeMaxDynamicSharedMemorySize, PREP_SMEM);
    prep_kernel<<<128, 256, PREP_SMEM>>>(phi, state, A, Bin, traj, tail);

    cudaFuncSetAttribute(sim_mma_kernel, cudaFuncAttributeMaxDynamicSharedMemorySize, SMEM_BYTES);
    sim_mma_kernel<<<dim3(T_ / (NTILE * 128), R_ / 128), 256, SMEM_BYTES>>>(out);
}

// round 15
// speedup vs baseline: 1.0409x; 1.0409x over previous
#include <cuda_runtime.h>
#include <cuda_bf16.h>
#include <cstdint>

#define B_  512
#define M_  16
#define D_  128
#define P_  16
#define T_  4096
#define R_  (B_*M_)          // 8192 rows

// ---- device-global scratch (no allocations allowed) ----
__device__ __nv_bfloat16 g_nsh[R_ * D_];
__device__ __nv_bfloat16 g_nsl[R_ * D_];
__device__ __nv_bfloat16 g_tjh[T_ * D_];
__device__ __nv_bfloat16 g_tjl[T_ * D_];
__device__ float g_ssq[R_];
__device__ float g_tsq[T_];

// ---------------------------------------------------------------- helpers
__device__ __forceinline__ uint32_t smem_u32(const void* p) {
    uint32_t a;
    asm("{ .reg .u64 t; cvta.to.shared.u64 t, %1; cvt.u32.u64 %0, t; }" : "=r"(a) : "l"(p));
    return a;
}
__device__ __forceinline__ float ex2a(float x) {
    float r; asm("ex2.approx.f32 %0, %1;" : "=f"(r) : "f"(x)); return r;
}
__device__ __forceinline__ float rcpa(float x) {
    float r; asm("rcp.approx.f32 %0, %1;" : "=f"(r) : "f"(x)); return r;
}
__device__ __forceinline__ float fast_tanh(float x) {
    const float TWO_L2E = 2.8853900817779268f;
    float e = ex2a(x * TWO_L2E);
    return fmaf(-2.0f, rcpa(e + 1.0f), 1.0f);
}
__device__ __forceinline__ void cpasync16(uint32_t s, const void* g) {
    asm volatile("cp.async.cg.shared.global [%0], [%1], 16;" :: "r"(s), "l"(g));
}
#define CP_COMMIT() asm volatile("cp.async.commit_group;" ::: "memory")
#define CP_WAIT(n)  asm volatile("cp.async.wait_group %0;" :: "n"(n) : "memory")

__device__ __forceinline__ void ldsm4(uint32_t* r, uint32_t a) {
    asm volatile("ldmatrix.sync.aligned.m8n8.x4.shared.b16 {%0,%1,%2,%3}, [%4];"
        : "=r"(r[0]), "=r"(r[1]), "=r"(r[2]), "=r"(r[3]) : "r"(a));
}
__device__ __forceinline__ void ldsm4t(uint32_t* r, uint32_t a) {
    asm volatile("ldmatrix.sync.aligned.m8n8.x4.trans.shared.b16 {%0,%1,%2,%3}, [%4];"
        : "=r"(r[0]), "=r"(r[1]), "=r"(r[2]), "=r"(r[3]) : "r"(a));
}
__device__ __forceinline__ void mma_bf16(float* d, const uint32_t* a, const uint32_t* b) {
    asm volatile(
        "mma.sync.aligned.m16n8k16.row.col.f32.bf16.bf16.f32 "
        "{%0,%1,%2,%3}, {%4,%5,%6,%7}, {%8,%9}, {%0,%1,%2,%3};"
        : "+f"(d[0]), "+f"(d[1]), "+f"(d[2]), "+f"(d[3])
        : "r"(a[0]), "r"(a[1]), "r"(a[2]), "r"(a[3]), "r"(b[0]), "r"(b[1]));
}
__device__ __forceinline__ void split4(float4 v, uint32_t& hp0, uint32_t& hp1,
                                       uint32_t& lp0, uint32_t& lp1) {
    __nv_bfloat16 h0 = __float2bfloat16_rn(v.x), h1 = __float2bfloat16_rn(v.y);
    __nv_bfloat16 h2 = __float2bfloat16_rn(v.z), h3 = __float2bfloat16_rn(v.w);
    __nv_bfloat16 l0 = __float2bfloat16_rn(v.x - __bfloat162float(h0));
    __nv_bfloat16 l1 = __float2bfloat16_rn(v.y - __bfloat162float(h1));
    __nv_bfloat16 l2 = __float2bfloat16_rn(v.z - __bfloat162float(h2));
    __nv_bfloat16 l3 = __float2bfloat16_rn(v.w - __bfloat162float(h3));
    hp0 = (uint32_t)__bfloat16_as_ushort(h0) | ((uint32_t)__bfloat16_as_ushort(h1) << 16);
    hp1 = (uint32_t)__bfloat16_as_ushort(h2) | ((uint32_t)__bfloat16_as_ushort(h3) << 16);
    lp0 = (uint32_t)__bfloat16_as_ushort(l0) | ((uint32_t)__bfloat16_as_ushort(l1) << 16);
    lp1 = (uint32_t)__bfloat16_as_ushort(l2) | ((uint32_t)__bfloat16_as_ushort(l3) << 16);
}

// ---------------------------------------------------------------------------
// Kernel 1: fused prep v3 — 2 CTAs/SM for the ns part.
//  blockIdx.x < 128 : trajectory hi/lo split + tsq (32 rows per CTA) — cheap,
//                     scheduled first so they drain early.
//  blockIdx.x >= 128: ns HMMA, CTA = (m = x>>4, 32-row tile b0 = (x&15)*32).
//                     smem: S 2x9.5K + W 2x38.25K + ssq = 97.9KB -> 2 CTAs/SM.
// Same strides/layout/MMA as the measured-good R10 prep; mt loop drops to 1.
// ---------------------------------------------------------------------------
#define PS_STRIDE 304
#define PW_STRIDE 272
#define POFF_SL  9728
#define POFF_WH  19456
#define POFF_WL  58624
#define POFF_SSQ 97792
#define PREP_SMEM 97920

__global__ __launch_bounds__(256, 2) void prep_kernel(
    const float* __restrict__ phi, const float* __restrict__ state,
    const float* __restrict__ A,   const float* __restrict__ Bin,
    const float* __restrict__ tj,  float* __restrict__ tail)
{
    const int tid = threadIdx.x;
    if (blockIdx.x < 128) {
        const int blk = blockIdx.x;
        const int wrp = tid >> 5;
        const int lid = tid & 31;
#pragma unroll
        for (int rr = 0; rr < 4; rr++) {
            const int row = blk * 32 + wrp * 4 + rr;
            float4 v = reinterpret_cast<const float4*>(tj)[row * 32 + lid];
            uint32_t hp0, hp1, lp0, lp1;
            split4(v, hp0, hp1, lp0, lp1);
            uint32_t* oh = reinterpret_cast<uint32_t*>(g_tjh) + row * 64 + lid * 2;
            uint32_t* ol = reinterpret_cast<uint32_t*>(g_tjl) + row * 64 + lid * 2;
            oh[0] = hp0; oh[1] = hp1;
            ol[0] = lp0; ol[1] = lp1;
            float s = v.x*v.x + v.y*v.y + v.z*v.z + v.w*v.w;
#pragma unroll
            for (int o = 16; o > 0; o >>= 1) s += __shfl_xor_sync(0xFFFFFFFFu, s, o);
            if (lid == 0) g_tsq[row] = s;
        }
        return;
    }

    extern __shared__ __align__(1024) char smem[];
    const uint32_t sb = smem_u32(smem);
    const int bx = blockIdx.x - 128;
    const int m  = bx >> 4;
    const int b0 = (bx & 15) * 32;
    const int wid = tid >> 5;
    const int lid = tid & 31;
    const int warp_m = (wid >> 2) * 16;      // rows 0-15 / 16-31
    const int warp_n = (wid & 3) * 32;

    if (tid < 32) reinterpret_cast<float*>(smem + POFF_SSQ)[tid] = 0.0f;

    {
        const float4* s4 = reinterpret_cast<const float4*>(state);
        for (int i = tid; i < 32 * 32; i += 256) {
            int r = i >> 5, c4 = i & 31;
            float4 v = s4[(b0 + r) * 32 + c4];
            uint32_t h0, h1, l0, l1;
            split4(v, h0, h1, l0, l1);
            uint32_t off = (uint32_t)r * PS_STRIDE + (uint32_t)c4 * 8;
            *reinterpret_cast<uint2*>(smem + off)           = make_uint2(h0, h1);
            *reinterpret_cast<uint2*>(smem + POFF_SL + off) = make_uint2(l0, l1);
        }
        const float4* p4 = reinterpret_cast<const float4*>(phi);
        for (int i = tid; i < 32 * 4; i += 256) {
            int r = i >> 2, c4 = i & 3;
            float4 v = p4[(b0 + r) * 4 + c4];
            uint32_t h0, h1, l0, l1;
            split4(v, h0, h1, l0, l1);
            uint32_t off = (uint32_t)r * PS_STRIDE + 256u + (uint32_t)c4 * 8;
            *reinterpret_cast<uint2*>(smem + off)           = make_uint2(h0, h1);
            *reinterpret_cast<uint2*>(smem + POFF_SL + off) = make_uint2(l0, l1);
        }
        const float4* a4 = reinterpret_cast<const float4*>(A) + (size_t)m * 4096;
        for (int i = tid; i < 128 * 32; i += 256) {
            int dd = i >> 5, c4 = i & 31;
            float4 v = a4[dd * 32 + c4];
            uint32_t h0, h1, l0, l1;
            split4(v, h0, h1, l0, l1);
            uint32_t off = (uint32_t)dd * PW_STRIDE + (uint32_t)c4 * 8;
            *reinterpret_cast<uint2*>(smem + POFF_WH + off) = make_uint2(h0, h1);
            *reinterpret_cast<uint2*>(smem + POFF_WL + off) = make_uint2(l0, l1);
        }
        const float4* b4 = reinterpret_cast<const float4*>(Bin) + (size_t)m * 512;
        for (int i = tid; i < 16 * 32; i += 256) {
            int p = i >> 5, c4 = i & 31;
            float4 v = b4[p * 32 + c4];
            uint32_t h0, h1, l0, l1;
            split4(v, h0, h1, l0, l1);
            uint32_t off = (uint32_t)(128 + p) * PW_STRIDE + (uint32_t)c4 * 8;
            *reinterpret_cast<uint2*>(smem + POFF_WH + off) = make_uint2(h0, h1);
            *reinterpret_cast<uint2*>(smem + POFF_WL + off) = make_uint2(l0, l1);
        }
    }
    __syncthreads();

    float d[4][4];
#pragma unroll
    for (int b = 0; b < 4; b++)
#pragma unroll
        for (int c = 0; c < 4; c++) d[b][c] = 0.0f;

    const uint32_t aRow  = (uint32_t)(warp_m + (lid & 15)) * PS_STRIDE + ((uint32_t)(lid >> 4) & 1) * 16u;
    const uint32_t bKrow = (uint32_t)(lid & 15) * PW_STRIDE;
    const uint32_t bNcol = ((uint32_t)warp_n + (((uint32_t)lid >> 4) & 1) * 8u) * 2u;

#pragma unroll
    for (int ks = 0; ks < 9; ks++) {
        uint32_t bqh[2][4], bql[2][4];
#pragma unroll
        for (int np = 0; np < 2; np++) {
            const uint32_t bo = sb + POFF_WH + (uint32_t)ks * 16u * PW_STRIDE
                              + bKrow + bNcol + (uint32_t)np * 32u;
            ldsm4t(bqh[np], bo);
            ldsm4t(bql[np], bo + (POFF_WL - POFF_WH));
        }
        uint32_t ah[4], al[4];
        const uint32_t ao = sb + aRow + (uint32_t)ks * 32u;
        ldsm4(ah, ao);
        ldsm4(al, ao + POFF_SL);
#pragma unroll
        for (int nt = 0; nt < 4; nt++) {
            const uint32_t* bh = &bqh[nt >> 1][(nt & 1) * 2];
            const uint32_t* bl = &bql[nt >> 1][(nt & 1) * 2];
            mma_bf16(d[nt], ah, bh);
            mma_bf16(d[nt], ah, bl);
            mma_bf16(d[nt], al, bh);
        }
    }

    float* ssq_s = reinterpret_cast<float*>(smem + POFF_SSQ);
    {
        const int lr  = warp_m + (lid >> 2);
        const int rg0 = (b0 + lr) * M_ + m;
        const int rg1 = (b0 + lr + 8) * M_ + m;
        float s0 = 0.0f, s1 = 0.0f;
#pragma unroll
        for (int nt = 0; nt < 4; nt++) {
            const int lc = warp_n + nt * 8 + (lid & 3) * 2;
            float v0 = fast_tanh(d[nt][0]);
            float v1 = fast_tanh(d[nt][1]);
            float v2 = fast_tanh(d[nt][2]);
            float v3 = fast_tanh(d[nt][3]);
            s0 += v0 * v0 + v1 * v1;
            s1 += v2 * v2 + v3 * v3;
            __nv_bfloat16 h0 = __float2bfloat16_rn(v0), h1 = __float2bfloat16_rn(v1);
            __nv_bfloat16 h2 = __float2bfloat16_rn(v2), h3 = __float2bfloat16_rn(v3);
            uint32_t hp0 = (uint32_t)__bfloat16_as_ushort(h0) | ((uint32_t)__bfloat16_as_ushort(h1) << 16);
            uint32_t hp1 = (uint32_t)__bfloat16_as_ushort(h2) | ((uint32_t)__bfloat16_as_ushort(h3) << 16);
            __nv_bfloat16 q0 = __float2bfloat16_rn(v0 - __bfloat162float(h0));
            __nv_bfloat16 q1 = __float2bfloat16_rn(v1 - __bfloat162float(h1));
            __nv_bfloat16 q2 = __float2bfloat16_rn(v2 - __bfloat162float(h2));
            __nv_bfloat16 q3 = __float2bfloat16_rn(v3 - __bfloat162float(h3));
            uint32_t lp0 = (uint32_t)__bfloat16_as_ushort(q0) | ((uint32_t)__bfloat16_as_ushort(q1) << 16);
            uint32_t lp1 = (uint32_t)__bfloat16_as_ushort(q2) | ((uint32_t)__bfloat16_as_ushort(q3) << 16);
            *reinterpret_cast<uint32_t*>(g_nsh + (size_t)rg0 * D_ + lc) = hp0;
            *reinterpret_cast<uint32_t*>(g_nsh + (size_t)rg1 * D_ + lc) = hp1;
            *reinterpret_cast<uint32_t*>(g_nsl + (size_t)rg0 * D_ + lc) = lp0;
            *reinterpret_cast<uint32_t*>(g_nsl + (size_t)rg1 * D_ + lc) = lp1;
            if (tail) {
                *reinterpret_cast<float2*>(tail + (size_t)rg0 * D_ + lc) = make_float2(v0, v1);
                *reinterpret_cast<float2*>(tail + (size_t)rg1 * D_ + lc) = make_float2(v2, v3);
            }
        }
        s0 += __shfl_xor_sync(0xFFFFFFFFu, s0, 1);
        s0 += __shfl_xor_sync(0xFFFFFFFFu, s0, 2);
        s1 += __shfl_xor_sync(0xFFFFFFFFu, s1, 1);
        s1 += __shfl_xor_sync(0xFFFFFFFFu, s1, 2);
        if ((lid & 3) == 0) {
            atomicAdd(&ssq_s[lr], s0);
            atomicAdd(&ssq_s[lr + 8], s1);
        }
    }
    __syncthreads();
    if (tid < 32) g_ssq[(b0 + tid) * M_ + m] = ssq_s[tid];
}

// ---------------------------------------------------------------------------
// Kernel 2 (R10 verbatim — measured best, 76.6us): A-resident + 2 t-tiles,
// B double-buffered k32 chunks, two syncs/chunk, norms in smem. 2 CTAs/SM.
// ---------------------------------------------------------------------------
#define OFF_AL   32768
#define OFF_B    65536
#define BSTG     16384
#define OFF_SSQ  98304
#define OFF_TSQ  98816
#define SMEM_BYTES 99840
#define NTILE 2
#define NCHUNK (NTILE * 4)

__global__ __launch_bounds__(256, 2) void sim_mma_kernel(float* __restrict__ out)
{
    extern __shared__ __align__(1024) char smem[];
    const uint32_t sb = smem_u32(smem);
    const int tid = threadIdx.x;
    const int wid = tid >> 5;
    const int lid = tid & 31;
    const int warp_m = (wid >> 2) * 64;
    const int warp_n = (wid & 3) * 32;
    const int r0 = blockIdx.y * 128;
    const int t0 = blockIdx.x * (NTILE * 128);

    // ---- A resident fill (one commit group)
    {
        const __nv_bfloat16* srcH = g_nsh + (size_t)r0 * D_;
        const __nv_bfloat16* srcL = g_nsl + (size_t)r0 * D_;
#pragma unroll
        for (int it = 0; it < 8; it++) {
            int i = tid + it * 256;           // 0..2047
            int r = i >> 4, g = i & 15;
            uint32_t dst = (uint32_t)r * 256u + (uint32_t)((g ^ (r & 7)) << 4);
            cpasync16(sb + dst,           srcH + r * D_ + g * 8);
            cpasync16(sb + OFF_AL + dst,  srcL + r * D_ + g * 8);
        }
    }
    CP_COMMIT();

    // fill B k32 chunk c (0..NCHUNK-1) into slot c&1
    auto fillB = [&](int c) {
        const uint32_t sbase = sb + OFF_B + (uint32_t)(c & 1) * BSTG;
        const int tile = c >> 2, kc = c & 3;
        const __nv_bfloat16* srcH = g_tjh + (size_t)(t0 + tile * 128) * D_ + kc * 32;
        const __nv_bfloat16* srcL = g_tjl + (size_t)(t0 + tile * 128) * D_ + kc * 32;
#pragma unroll
        for (int it = 0; it < 4; it++) {
            int idx = tid + it * 256;          // 0..1023
            int hl = idx >> 9, rem = idx & 511;
            int r = rem >> 2, cc = rem & 3;
            uint32_t slot = (uint32_t)(cc ^ (r & 3) ^ (((r >> 2) & 1) << 1));
            uint32_t dst = sbase + (uint32_t)hl * 8192u + (uint32_t)r * 64u + (slot << 4);
            cpasync16(dst, (hl ? srcL : srcH) + r * D_ + cc * 8);
        }
    };

    fillB(0); CP_COMMIT();
    fillB(1); CP_COMMIT();

    // norms
    if (tid < 128) reinterpret_cast<float*>(smem + OFF_SSQ)[tid] = g_ssq[r0 + tid];
    reinterpret_cast<float*>(smem + OFF_TSQ)[tid] = g_tsq[t0 + tid];

    float d[4][4][4];
#pragma unroll
    for (int a = 0; a < 4; a++)
#pragma unroll
        for (int b = 0; b < 4; b++)
#pragma unroll
            for (int c = 0; c < 4; c++) d[a][b][c] = 0.0f;

    // per-lane addressing
    const uint32_t ra = (uint32_t)(warp_m + (lid & 15));
    const uint32_t aSel = (lid >> 4) & 1;
    const uint32_t rxA = (ra & 7);
    uint32_t aBase[4];
#pragma unroll
    for (int mt = 0; mt < 4; mt++) aBase[mt] = sb + (ra + mt * 16) * 256u;
    const uint32_t rb = (uint32_t)(warp_n + ((lid & 16) >> 1) + (lid & 7));
    const uint32_t bSel = (lid >> 3) & 1;
    const uint32_t rxB = (rb & 3) ^ (((rb >> 2) & 1) << 1);
    uint32_t rowOffB[2];
#pragma unroll
    for (int np = 0; np < 2; np++) rowOffB[np] = (rb + np * 16) * 64u;

    const float* s_ssq = reinterpret_cast<const float*>(smem + OFF_SSQ);
    const float* s_tsq = reinterpret_cast<const float*>(smem + OFF_TSQ);
    const float NL2E = -1.4426950408889634f;
    const float SC64 = 5.421010862427522e-20f;

#pragma unroll
    for (int i = 0; i < NCHUNK; i++) {
        if (i == 0)              { CP_WAIT(1); }   // A + B0 done, B1 pending
        else if (i < NCHUNK - 1) { CP_WAIT(1); }   // B(i) done, B(i+1) pending
        else                     { CP_WAIT(0); }
        __syncthreads();

        const uint32_t sbs = sb + OFF_B + (uint32_t)(i & 1) * BSTG;
#pragma unroll
        for (int ksub = 0; ksub < 2; ksub++) {
            const uint32_t cB = (uint32_t)(ksub * 2) + bSel;
            uint32_t bqh[2][4], bql[2][4];
#pragma unroll
            for (int np = 0; np < 2; np++) {
                const uint32_t bo = sbs + rowOffB[np] + (((cB ^ rxB)) << 4);
                ldsm4(bqh[np], bo);
                ldsm4(bql[np], bo + 8192u);
            }
            const int ks16 = (i & 3) * 2 + ksub;         // 0..7 within K=128
            const uint32_t gsel = (uint32_t)(((uint32_t)(ks16 * 2) + aSel) ^ rxA) << 4;
#pragma unroll
            for (int mt = 0; mt < 4; mt++) {
                uint32_t ah[4], al[4];
                ldsm4(ah, aBase[mt] + gsel);
                ldsm4(al, aBase[mt] + OFF_AL + gsel);
#pragma unroll
                for (int nt = 0; nt < 4; nt++) {
                    const uint32_t* bh = &bqh[nt >> 1][(nt & 1) * 2];
                    const uint32_t* bl = &bql[nt >> 1][(nt & 1) * 2];
                    mma_bf16(d[mt][nt], ah, bh);
                    mma_bf16(d[mt][nt], ah, bl);
                    mma_bf16(d[mt][nt], al, bh);
                }
            }
        }

        // ---- per-t-tile epilogue after last chunk of the tile
        if ((i & 3) == 3) {
            const int tile = i >> 2;
#pragma unroll
            for (int mt = 0; mt < 4; mt++) {
                const int lr = warp_m + mt * 16 + (lid >> 2);
                const float sq0 = s_ssq[lr];
                const float sq1 = s_ssq[lr + 8];
                float* row0 = out + (size_t)(r0 + lr) * T_ + t0 + tile * 128;
                float* row1 = row0 + (size_t)8 * T_;
#pragma unroll
                for (int nt = 0; nt < 4; nt++) {
                    const int lc = warp_n + nt * 8 + (lid & 3) * 2;
                    const float tq0 = s_tsq[tile * 128 + lc];
                    const float tq1 = s_tsq[tile * 128 + lc + 1];
                    float in[4] = { sq0 + tq0, sq0 + tq1, sq1 + tq0, sq1 + tq1 };
                    float o[4];
#pragma unroll
                    for (int j = 0; j < 4; j++) {
                        float dd = fmaf(-2.0f, d[mt][nt][j], in[j]);
                        dd = fmaxf(dd, 0.0f);
                        float t = NL2E * dd;
                        float tb = t, sc = 1.0f;
                        if (t < -80.0f) { tb = t + 64.0f; sc = SC64; }
                        o[j] = ex2a(tb) * sc;
                        d[mt][nt][j] = 0.0f;
                    }
                    *reinterpret_cast<float2*>(row0 + lc) = make_float2(o[0], o[1]);
                    *reinterpret_cast<float2*>(row1 + lc) = make_float2(o[2], o[3]);
                }
            }
        }
        __syncthreads();                    // slot i&1 fully consumed
        if (i + 2 < NCHUNK) { fillB(i + 2); CP_COMMIT(); }
    }
}

// ---------------------------------------------------------------------------
extern "C" void kernel_launch(void* const* d_in, const int* in_sizes, int n_in,
                              void* d_out, int out_size) {
    const float *phi = nullptr, *state = nullptr, *traj = nullptr, *A = nullptr, *Bin = nullptr;
    for (int i = 0; i < n_in; i++) {
        switch (in_sizes[i]) {
            case B_ * P_:      phi   = (const float*)d_in[i]; break;  // 8192
            case B_ * D_:      state = (const float*)d_in[i]; break;  // 65536
            case T_ * D_:      traj  = (const float*)d_in[i]; break;  // 524288
            case M_ * D_ * D_: A     = (const float*)d_in[i]; break;  // 262144
            case M_ * P_ * D_: Bin   = (const float*)d_in[i]; break;  // 32768
        }
    }
    float* out = (float*)d_out;
    const long long SIMSZ = (long long)R_ * T_;
    const long long NSSZ  = (long long)R_ * D_;
    float* tail = ((long long)out_size >= SIMSZ + NSSZ) ? out + SIMSZ : nullptr;

    cudaFuncSetAttribute(prep_kernel, cudaFuncAttributeMaxDynamicSharedMemorySize, PREP_SMEM);
    prep_kernel<<<384, 256, PREP_SMEM>>>(phi, state, A, Bin, traj, tail);

    cudaFuncSetAttribute(sim_mma_kernel, cudaFuncAttributeMaxDynamicSharedMemorySize, SMEM_BYTES);
    sim_mma_kernel<<<dim3(T_ / (NTILE * 128), R_ / 128), 256, SMEM_BYTES>>>(out);
}

// round 17
// speedup vs baseline: 1.0427x; 1.0017x over previous
#include <cuda_runtime.h>
#include <cuda_bf16.h>
#include <cstdint>

#define B_  512
#define M_  16
#define D_  128
#define P_  16
#define T_  4096
#define R_  (B_*M_)          // 8192 rows

// ---- device-global scratch (no allocations allowed) ----
__device__ __nv_bfloat16 g_nsh[R_ * D_];
__device__ __nv_bfloat16 g_nsl[R_ * D_];
__device__ __nv_bfloat16 g_tjh[T_ * D_];
__device__ __nv_bfloat16 g_tjl[T_ * D_];
__device__ float g_ssq[R_];
__device__ float g_tsq[T_];

// ---------------------------------------------------------------- helpers
__device__ __forceinline__ uint32_t smem_u32(const void* p) {
    uint32_t a;
    asm("{ .reg .u64 t; cvta.to.shared.u64 t, %1; cvt.u32.u64 %0, t; }" : "=r"(a) : "l"(p));
    return a;
}
__device__ __forceinline__ float ex2a(float x) {
    float r; asm("ex2.approx.f32 %0, %1;" : "=f"(r) : "f"(x)); return r;
}
__device__ __forceinline__ float rcpa(float x) {
    float r; asm("rcp.approx.f32 %0, %1;" : "=f"(r) : "f"(x)); return r;
}
__device__ __forceinline__ float fast_tanh(float x) {
    const float TWO_L2E = 2.8853900817779268f;
    float e = ex2a(x * TWO_L2E);
    return fmaf(-2.0f, rcpa(e + 1.0f), 1.0f);
}
__device__ __forceinline__ void cpasync16(uint32_t s, const void* g) {
    asm volatile("cp.async.cg.shared.global [%0], [%1], 16;" :: "r"(s), "l"(g));
}
#define CP_COMMIT() asm volatile("cp.async.commit_group;" ::: "memory")
#define CP_WAIT(n)  asm volatile("cp.async.wait_group %0;" :: "n"(n) : "memory")

__device__ __forceinline__ void ldsm4(uint32_t* r, uint32_t a) {
    asm volatile("ldmatrix.sync.aligned.m8n8.x4.shared.b16 {%0,%1,%2,%3}, [%4];"
        : "=r"(r[0]), "=r"(r[1]), "=r"(r[2]), "=r"(r[3]) : "r"(a));
}
__device__ __forceinline__ void ldsm4t(uint32_t* r, uint32_t a) {
    asm volatile("ldmatrix.sync.aligned.m8n8.x4.trans.shared.b16 {%0,%1,%2,%3}, [%4];"
        : "=r"(r[0]), "=r"(r[1]), "=r"(r[2]), "=r"(r[3]) : "r"(a));
}
__device__ __forceinline__ void mma_bf16(float* d, const uint32_t* a, const uint32_t* b) {
    asm volatile(
        "mma.sync.aligned.m16n8k16.row.col.f32.bf16.bf16.f32 "
        "{%0,%1,%2,%3}, {%4,%5,%6,%7}, {%8,%9}, {%0,%1,%2,%3};"
        : "+f"(d[0]), "+f"(d[1]), "+f"(d[2]), "+f"(d[3])
        : "r"(a[0]), "r"(a[1]), "r"(a[2]), "r"(a[3]), "r"(b[0]), "r"(b[1]));
}
__device__ __forceinline__ void split4(float4 v, uint32_t& hp0, uint32_t& hp1,
                                       uint32_t& lp0, uint32_t& lp1) {
    __nv_bfloat16 h0 = __float2bfloat16_rn(v.x), h1 = __float2bfloat16_rn(v.y);
    __nv_bfloat16 h2 = __float2bfloat16_rn(v.z), h3 = __float2bfloat16_rn(v.w);
    __nv_bfloat16 l0 = __float2bfloat16_rn(v.x - __bfloat162float(h0));
    __nv_bfloat16 l1 = __float2bfloat16_rn(v.y - __bfloat162float(h1));
    __nv_bfloat16 l2 = __float2bfloat16_rn(v.z - __bfloat162float(h2));
    __nv_bfloat16 l3 = __float2bfloat16_rn(v.w - __bfloat162float(h3));
    hp0 = (uint32_t)__bfloat16_as_ushort(h0) | ((uint32_t)__bfloat16_as_ushort(h1) << 16);
    hp1 = (uint32_t)__bfloat16_as_ushort(h2) | ((uint32_t)__bfloat16_as_ushort(h3) << 16);
    lp0 = (uint32_t)__bfloat16_as_ushort(l0) | ((uint32_t)__bfloat16_as_ushort(l1) << 16);
    lp1 = (uint32_t)__bfloat16_as_ushort(l2) | ((uint32_t)__bfloat16_as_ushort(l3) << 16);
}

// ---------------------------------------------------------------------------
// Kernel 1: fused prep v3 — 2 CTAs/SM for the ns part.
//  blockIdx.x < 128 : trajectory hi/lo split + tsq (32 rows per CTA)
//  blockIdx.x >= 128: ns HMMA, CTA = (m = x>>4, 32-row tile b0 = (x&15)*32).
//                     smem: S 2x9.5K + W 2x38.25K + ssq = 97.9KB -> 2 CTAs/SM.
// ---------------------------------------------------------------------------
#define PS_STRIDE 304
#define PW_STRIDE 272
#define POFF_SL  9728
#define POFF_WH  19456
#define POFF_WL  58624
#define POFF_SSQ 97792
#define PREP_SMEM 97920

__global__ __launch_bounds__(256, 2) void prep_kernel(
    const float* __restrict__ phi, const float* __restrict__ state,
    const float* __restrict__ A,   const float* __restrict__ Bin,
    const float* __restrict__ tj,  float* __restrict__ tail)
{
    const int tid = threadIdx.x;
    if (blockIdx.x < 128) {
        const int blk = blockIdx.x;
        const int wrp = tid >> 5;
        const int lid = tid & 31;
#pragma unroll
        for (int rr = 0; rr < 4; rr++) {
            const int row = blk * 32 + wrp * 4 + rr;
            float4 v = reinterpret_cast<const float4*>(tj)[row * 32 + lid];
            uint32_t hp0, hp1, lp0, lp1;
            split4(v, hp0, hp1, lp0, lp1);
            uint32_t* oh = reinterpret_cast<uint32_t*>(g_tjh) + row * 64 + lid * 2;
            uint32_t* ol = reinterpret_cast<uint32_t*>(g_tjl) + row * 64 + lid * 2;
            oh[0] = hp0; oh[1] = hp1;
            ol[0] = lp0; ol[1] = lp1;
            float s = v.x*v.x + v.y*v.y + v.z*v.z + v.w*v.w;
#pragma unroll
            for (int o = 16; o > 0; o >>= 1) s += __shfl_xor_sync(0xFFFFFFFFu, s, o);
            if (lid == 0) g_tsq[row] = s;
        }
        return;
    }

    extern __shared__ __align__(1024) char smem[];
    const uint32_t sb = smem_u32(smem);
    const int bx = blockIdx.x - 128;
    const int m  = bx >> 4;
    const int b0 = (bx & 15) * 32;
    const int wid = tid >> 5;
    const int lid = tid & 31;
    const int warp_m = (wid >> 2) * 16;      // rows 0-15 / 16-31
    const int warp_n = (wid & 3) * 32;

    if (tid < 32) reinterpret_cast<float*>(smem + POFF_SSQ)[tid] = 0.0f;

    {
        const float4* s4 = reinterpret_cast<const float4*>(state);
        for (int i = tid; i < 32 * 32; i += 256) {
            int r = i >> 5, c4 = i & 31;
            float4 v = s4[(b0 + r) * 32 + c4];
            uint32_t h0, h1, l0, l1;
            split4(v, h0, h1, l0, l1);
            uint32_t off = (uint32_t)r * PS_STRIDE + (uint32_t)c4 * 8;
            *reinterpret_cast<uint2*>(smem + off)           = make_uint2(h0, h1);
            *reinterpret_cast<uint2*>(smem + POFF_SL + off) = make_uint2(l0, l1);
        }
        const float4* p4 = reinterpret_cast<const float4*>(phi);
        for (int i = tid; i < 32 * 4; i += 256) {
            int r = i >> 2, c4 = i & 3;
            float4 v = p4[(b0 + r) * 4 + c4];
            uint32_t h0, h1, l0, l1;
            split4(v, h0, h1, l0, l1);
            uint32_t off = (uint32_t)r * PS_STRIDE + 256u + (uint32_t)c4 * 8;
            *reinterpret_cast<uint2*>(smem + off)           = make_uint2(h0, h1);
            *reinterpret_cast<uint2*>(smem + POFF_SL + off) = make_uint2(l0, l1);
        }
        const float4* a4 = reinterpret_cast<const float4*>(A) + (size_t)m * 4096;
        for (int i = tid; i < 128 * 32; i += 256) {
            int dd = i >> 5, c4 = i & 31;
            float4 v = a4[dd * 32 + c4];
            uint32_t h0, h1, l0, l1;
            split4(v, h0, h1, l0, l1);
            uint32_t off = (uint32_t)dd * PW_STRIDE + (uint32_t)c4 * 8;
            *reinterpret_cast<uint2*>(smem + POFF_WH + off) = make_uint2(h0, h1);
            *reinterpret_cast<uint2*>(smem + POFF_WL + off) = make_uint2(l0, l1);
        }
        const float4* b4 = reinterpret_cast<const float4*>(Bin) + (size_t)m * 512;
        for (int i = tid; i < 16 * 32; i += 256) {
            int p = i >> 5, c4 = i & 31;
            float4 v = b4[p * 32 + c4];
            uint32_t h0, h1, l0, l1;
            split4(v, h0, h1, l0, l1);
            uint32_t off = (uint32_t)(128 + p) * PW_STRIDE + (uint32_t)c4 * 8;
            *reinterpret_cast<uint2*>(smem + POFF_WH + off) = make_uint2(h0, h1);
            *reinterpret_cast<uint2*>(smem + POFF_WL + off) = make_uint2(l0, l1);
        }
    }
    __syncthreads();

    float d[4][4];
#pragma unroll
    for (int b = 0; b < 4; b++)
#pragma unroll
        for (int c = 0; c < 4; c++) d[b][c] = 0.0f;

    const uint32_t aRow  = (uint32_t)(warp_m + (lid & 15)) * PS_STRIDE + ((uint32_t)(lid >> 4) & 1) * 16u;
    const uint32_t bKrow = (uint32_t)(lid & 15) * PW_STRIDE;
    const uint32_t bNcol = ((uint32_t)warp_n + (((uint32_t)lid >> 4) & 1) * 8u) * 2u;

#pragma unroll
    for (int ks = 0; ks < 9; ks++) {
        uint32_t bqh[2][4], bql[2][4];
#pragma unroll
        for (int np = 0; np < 2; np++) {
            const uint32_t bo = sb + POFF_WH + (uint32_t)ks * 16u * PW_STRIDE
                              + bKrow + bNcol + (uint32_t)np * 32u;
            ldsm4t(bqh[np], bo);
            ldsm4t(bql[np], bo + (POFF_WL - POFF_WH));
        }
        uint32_t ah[4], al[4];
        const uint32_t ao = sb + aRow + (uint32_t)ks * 32u;
        ldsm4(ah, ao);
        ldsm4(al, ao + POFF_SL);
#pragma unroll
        for (int nt = 0; nt < 4; nt++) {
            const uint32_t* bh = &bqh[nt >> 1][(nt & 1) * 2];
            const uint32_t* bl = &bql[nt >> 1][(nt & 1) * 2];
            mma_bf16(d[nt], ah, bh);
            mma_bf16(d[nt], ah, bl);
            mma_bf16(d[nt], al, bh);
        }
    }

    float* ssq_s = reinterpret_cast<float*>(smem + POFF_SSQ);
    {
        const int lr  = warp_m + (lid >> 2);
        const int rg0 = (b0 + lr) * M_ + m;
        const int rg1 = (b0 + lr + 8) * M_ + m;
        float s0 = 0.0f, s1 = 0.0f;
#pragma unroll
        for (int nt = 0; nt < 4; nt++) {
            const int lc = warp_n + nt * 8 + (lid & 3) * 2;
            float v0 = fast_tanh(d[nt][0]);
            float v1 = fast_tanh(d[nt][1]);
            float v2 = fast_tanh(d[nt][2]);
            float v3 = fast_tanh(d[nt][3]);
            s0 += v0 * v0 + v1 * v1;
            s1 += v2 * v2 + v3 * v3;
            __nv_bfloat16 h0 = __float2bfloat16_rn(v0), h1 = __float2bfloat16_rn(v1);
            __nv_bfloat16 h2 = __float2bfloat16_rn(v2), h3 = __float2bfloat16_rn(v3);
            uint32_t hp0 = (uint32_t)__bfloat16_as_ushort(h0) | ((uint32_t)__bfloat16_as_ushort(h1) << 16);
            uint32_t hp1 = (uint32_t)__bfloat16_as_ushort(h2) | ((uint32_t)__bfloat16_as_ushort(h3) << 16);
            __nv_bfloat16 q0 = __float2bfloat16_rn(v0 - __bfloat162float(h0));
            __nv_bfloat16 q1 = __float2bfloat16_rn(v1 - __bfloat162float(h1));
            __nv_bfloat16 q2 = __float2bfloat16_rn(v2 - __bfloat162float(h2));
            __nv_bfloat16 q3 = __float2bfloat16_rn(v3 - __bfloat162float(h3));
            uint32_t lp0 = (uint32_t)__bfloat16_as_ushort(q0) | ((uint32_t)__bfloat16_as_ushort(q1) << 16);
            uint32_t lp1 = (uint32_t)__bfloat16_as_ushort(q2) | ((uint32_t)__bfloat16_as_ushort(q3) << 16);
            *reinterpret_cast<uint32_t*>(g_nsh + (size_t)rg0 * D_ + lc) = hp0;
            *reinterpret_cast<uint32_t*>(g_nsh + (size_t)rg1 * D_ + lc) = hp1;
            *reinterpret_cast<uint32_t*>(g_nsl + (size_t)rg0 * D_ + lc) = lp0;
            *reinterpret_cast<uint32_t*>(g_nsl + (size_t)rg1 * D_ + lc) = lp1;
            if (tail) {
                *reinterpret_cast<float2*>(tail + (size_t)rg0 * D_ + lc) = make_float2(v0, v1);
                *reinterpret_cast<float2*>(tail + (size_t)rg1 * D_ + lc) = make_float2(v2, v3);
            }
        }
        s0 += __shfl_xor_sync(0xFFFFFFFFu, s0, 1);
        s0 += __shfl_xor_sync(0xFFFFFFFFu, s0, 2);
        s1 += __shfl_xor_sync(0xFFFFFFFFu, s1, 1);
        s1 += __shfl_xor_sync(0xFFFFFFFFu, s1, 2);
        if ((lid & 3) == 0) {
            atomicAdd(&ssq_s[lr], s0);
            atomicAdd(&ssq_s[lr + 8], s1);
        }
    }
    __syncthreads();
    if (tid < 32) g_ssq[(b0 + tid) * M_ + m] = ssq_s[tid];
}

// ---------------------------------------------------------------------------
// Kernel 2 (R10 verbatim — measured best, ~75.6us): A-resident + 2 t-tiles,
// B double-buffered k32 chunks, two syncs/chunk, norms in smem. 2 CTAs/SM.
// ---------------------------------------------------------------------------
#define OFF_AL   32768
#define OFF_B    65536
#define BSTG     16384
#define OFF_SSQ  98304
#define OFF_TSQ  98816
#define SMEM_BYTES 99840
#define NTILE 2
#define NCHUNK (NTILE * 4)

__global__ __launch_bounds__(256, 2) void sim_mma_kernel(float* __restrict__ out)
{
    extern __shared__ __align__(1024) char smem[];
    const uint32_t sb = smem_u32(smem);
    const int tid = threadIdx.x;
    const int wid = tid >> 5;
    const int lid = tid & 31;
    const int warp_m = (wid >> 2) * 64;
    const int warp_n = (wid & 3) * 32;
    const int r0 = blockIdx.y * 128;
    const int t0 = blockIdx.x * (NTILE * 128);

    // ---- A resident fill (one commit group)
    {
        const __nv_bfloat16* srcH = g_nsh + (size_t)r0 * D_;
        const __nv_bfloat16* srcL = g_nsl + (size_t)r0 * D_;
#pragma unroll
        for (int it = 0; it < 8; it++) {
            int i = tid + it * 256;           // 0..2047
            int r = i >> 4, g = i & 15;
            uint32_t dst = (uint32_t)r * 256u + (uint32_t)((g ^ (r & 7)) << 4);
            cpasync16(sb + dst,           srcH + r * D_ + g * 8);
            cpasync16(sb + OFF_AL + dst,  srcL + r * D_ + g * 8);
        }
    }
    CP_COMMIT();

    // fill B k32 chunk c (0..NCHUNK-1) into slot c&1
    auto fillB = [&](int c) {
        const uint32_t sbase = sb + OFF_B + (uint32_t)(c & 1) * BSTG;
        const int tile = c >> 2, kc = c & 3;
        const __nv_bfloat16* srcH = g_tjh + (size_t)(t0 + tile * 128) * D_ + kc * 32;
        const __nv_bfloat16* srcL = g_tjl + (size_t)(t0 + tile * 128) * D_ + kc * 32;
#pragma unroll
        for (int it = 0; it < 4; it++) {
            int idx = tid + it * 256;          // 0..1023
            int hl = idx >> 9, rem = idx & 511;
            int r = rem >> 2, cc = rem & 3;
            uint32_t slot = (uint32_t)(cc ^ (r & 3) ^ (((r >> 2) & 1) << 1));
            uint32_t dst = sbase + (uint32_t)hl * 8192u + (uint32_t)r * 64u + (slot << 4);
            cpasync16(dst, (hl ? srcL : srcH) + r * D_ + cc * 8);
        }
    };

    fillB(0); CP_COMMIT();
    fillB(1); CP_COMMIT();

    // norms
    if (tid < 128) reinterpret_cast<float*>(smem + OFF_SSQ)[tid] = g_ssq[r0 + tid];
    reinterpret_cast<float*>(smem + OFF_TSQ)[tid] = g_tsq[t0 + tid];

    float d[4][4][4];
#pragma unroll
    for (int a = 0; a < 4; a++)
#pragma unroll
        for (int b = 0; b < 4; b++)
#pragma unroll
            for (int c = 0; c < 4; c++) d[a][b][c] = 0.0f;

    // per-lane addressing
    const uint32_t ra = (uint32_t)(warp_m + (lid & 15));
    const uint32_t aSel = (lid >> 4) & 1;
    const uint32_t rxA = (ra & 7);
    uint32_t aBase[4];
#pragma unroll
    for (int mt = 0; mt < 4; mt++) aBase[mt] = sb + (ra + mt * 16) * 256u;
    const uint32_t rb = (uint32_t)(warp_n + ((lid & 16) >> 1) + (lid & 7));
    const uint32_t bSel = (lid >> 3) & 1;
    const uint32_t rxB = (rb & 3) ^ (((rb >> 2) & 1) << 1);
    uint32_t rowOffB[2];
#pragma unroll
    for (int np = 0; np < 2; np++) rowOffB[np] = (rb + np * 16) * 64u;

    const float* s_ssq = reinterpret_cast<const float*>(smem + OFF_SSQ);
    const float* s_tsq = reinterpret_cast<const float*>(smem + OFF_TSQ);
    const float NL2E = -1.4426950408889634f;
    const float SC64 = 5.421010862427522e-20f;

#pragma unroll
    for (int i = 0; i < NCHUNK; i++) {
        if (i == 0)              { CP_WAIT(1); }   // A + B0 done, B1 pending
        else if (i < NCHUNK - 1) { CP_WAIT(1); }   // B(i) done, B(i+1) pending
        else                     { CP_WAIT(0); }
        __syncthreads();

        const uint32_t sbs = sb + OFF_B + (uint32_t)(i & 1) * BSTG;
#pragma unroll
        for (int ksub = 0; ksub < 2; ksub++) {
            const uint32_t cB = (uint32_t)(ksub * 2) + bSel;
            uint32_t bqh[2][4], bql[2][4];
#pragma unroll
            for (int np = 0; np < 2; np++) {
                const uint32_t bo = sbs + rowOffB[np] + (((cB ^ rxB)) << 4);
                ldsm4(bqh[np], bo);
                ldsm4(bql[np], bo + 8192u);
            }
            const int ks16 = (i & 3) * 2 + ksub;         // 0..7 within K=128
            const uint32_t gsel = (uint32_t)(((uint32_t)(ks16 * 2) + aSel) ^ rxA) << 4;
#pragma unroll
            for (int mt = 0; mt < 4; mt++) {
                uint32_t ah[4], al[4];
                ldsm4(ah, aBase[mt] + gsel);
                ldsm4(al, aBase[mt] + OFF_AL + gsel);
#pragma unroll
                for (int nt = 0; nt < 4; nt++) {
                    const uint32_t* bh = &bqh[nt >> 1][(nt & 1) * 2];
                    const uint32_t* bl = &bql[nt >> 1][(nt & 1) * 2];
                    mma_bf16(d[mt][nt], ah, bh);
                    mma_bf16(d[mt][nt], ah, bl);
                    mma_bf16(d[mt][nt], al, bh);
                }
            }
        }

        // ---- per-t-tile epilogue after last chunk of the tile
        if ((i & 3) == 3) {
            const int tile = i >> 2;
#pragma unroll
            for (int mt = 0; mt < 4; mt++) {
                const int lr = warp_m + mt * 16 + (lid >> 2);
                const float sq0 = s_ssq[lr];
                const float sq1 = s_ssq[lr + 8];
                float* row0 = out + (size_t)(r0 + lr) * T_ + t0 + tile * 128;
                float* row1 = row0 + (size_t)8 * T_;
#pragma unroll
                for (int nt = 0; nt < 4; nt++) {
                    const int lc = warp_n + nt * 8 + (lid & 3) * 2;
                    const float tq0 = s_tsq[tile * 128 + lc];
                    const float tq1 = s_tsq[tile * 128 + lc + 1];
                    float in[4] = { sq0 + tq0, sq0 + tq1, sq1 + tq0, sq1 + tq1 };
                    float o[4];
#pragma unroll
                    for (int j = 0; j < 4; j++) {
                        float dd = fmaf(-2.0f, d[mt][nt][j], in[j]);
                        dd = fmaxf(dd, 0.0f);
                        float t = NL2E * dd;
                        float tb = t, sc = 1.0f;
                        if (t < -80.0f) { tb = t + 64.0f; sc = SC64; }
                        o[j] = ex2a(tb) * sc;
                        d[mt][nt][j] = 0.0f;
                    }
                    *reinterpret_cast<float2*>(row0 + lc) = make_float2(o[0], o[1]);
                    *reinterpret_cast<float2*>(row1 + lc) = make_float2(o[2], o[3]);
                }
            }
        }
        __syncthreads();                    // slot i&1 fully consumed
        if (i + 2 < NCHUNK) { fillB(i + 2); CP_COMMIT(); }
    }
}

// ---------------------------------------------------------------------------
extern "C" void kernel_launch(void* const* d_in, const int* in_sizes, int n_in,
                              void* d_out, int out_size) {
    const float *phi = nullptr, *state = nullptr, *traj = nullptr, *A = nullptr, *Bin = nullptr;
    for (int i = 0; i < n_in; i++) {
        switch (in_sizes[i]) {
            case B_ * P_:      phi   = (const float*)d_in[i]; break;  // 8192
            case B_ * D_:      state = (const float*)d_in[i]; break;  // 65536
            case T_ * D_:      traj  = (const float*)d_in[i]; break;  // 524288
            case M_ * D_ * D_: A     = (const float*)d_in[i]; break;  // 262144
            case M_ * P_ * D_: Bin   = (const float*)d_in[i]; break;  // 32768
        }
    }
    float* out = (float*)d_out;
    const long long SIMSZ = (long long)R_ * T_;
    const long long NSSZ  = (long long)R_ * D_;
    float* tail = ((long long)out_size >= SIMSZ + NSSZ) ? out + SIMSZ : nullptr;

    cudaFuncSetAttribute(prep_kernel, cudaFuncAttributeMaxDynamicSharedMemorySize, PREP_SMEM);
    prep_kernel<<<384, 256, PREP_SMEM>>>(phi, state, A, Bin, traj, tail);

    cudaFuncSetAttribute(sim_mma_kernel, cudaFuncAttributeMaxDynamicSharedMemorySize, SMEM_BYTES);
    sim_mma_kernel<<<dim3(T_ / (NTILE * 128), R_ / 128), 256, SMEM_BYTES>>>(out);
}